// round 9
// baseline (speedup 1.0000x reference)
#include <cuda_runtime.h>
#include <cuda_bf16.h>
#include <math.h>

namespace {

constexpr int B  = 256;
constexpr int L  = 128;
constexpr int H  = 512;
constexpr int H4 = 2048;
constexpr int NC = 2560;   // combined decoder GEMM width: 512 (q) + 2048 (z from h)

// ---------------- device state (allocation-free scratch) ----------------
__device__ float g_h[2][B * H];                          // hidden, double buffered by parity
__device__ float g_c[B * H];                             // cell
__device__ float g_enc_out[(size_t)B * L * H];           // fp32 [b*L+l][h] (encw1 A input)
__device__ __nv_bfloat16 g_enc_outh[(size_t)B * L * H];  // bf16 [b][l][h] (attn context)
__device__ __nv_bfloat16 g_enc_w1h[(size_t)B * L * H];   // bf16 [b*L+l][h] (attn scores)
__device__ float g_ctx[B * H];                           // attention context
__device__ float g_dec_in[2][B];                         // decoder scalar input
__device__ float g_ew4[H4 * H];                          // enc_Wh, gate-interleaved rows n'=4h+g
__device__ float g_eb4[H4];                              // enc bias, interleaved
__device__ float g_ewi4[H4];                             // enc Wi (scalar input), interleaved
__device__ float g_wcomb[NC * H];                        // [w2 rows | dec Wh rows (interleaved)]
__device__ float g_dwic[H4 * H];                         // dec Wi (ctx part), interleaved rows
__device__ float g_db4[H4];
__device__ float g_dwi4[H4];                             // dec Wi last column, interleaved
__device__ float g_zpart[2 * B * H4];                    // split-K partials, [kz][b][n'=4h+g]
__device__ float g_cpart[2 * B * NC];                    // combined GEMM partials, [kz][b][0..2559]
__device__ int   g_cnt[256];                             // per-tile arrival counters

// ---------------- math helpers ----------------
__device__ __forceinline__ float sigmoid_acc(float x) {
    return 1.0f / (1.0f + __expf(-x));
}
__device__ __forceinline__ float tanh_acc(float x) {
    float e = __expf(-2.0f * fabsf(x));
    float r = (1.0f - e) / (1.0f + e);
    return copysignf(r, x);
}
__device__ __forceinline__ float tanh_fast(float x) {
    float y;
    asm("tanh.approx.f32 %0, %1;" : "=f"(y) : "f"(x));
    return y;
}

// ---------------- init ----------------
__global__ void k_init() {
    int i = blockIdx.x * blockDim.x + threadIdx.x;
    int stride = gridDim.x * blockDim.x;
    for (int j = i; j < B * H; j += stride) {
        g_h[0][j] = 0.0f;
        g_c[j]    = 0.0f;
    }
    if (i < B) g_dec_in[0][i] = 0.0f;
    if (i < 256) g_cnt[i] = 0;
}

// ---------------- one-time repacks ----------------
__global__ void k_repack_enc(const float* __restrict__ ewh,
                             const float* __restrict__ eb,
                             const float* __restrict__ ewi) {
    int i = blockIdx.x * blockDim.x + threadIdx.x;
    int stride = gridDim.x * blockDim.x;
    for (int j = i; j < H4 * H; j += stride) {
        int np = j >> 9;
        int k  = j & (H - 1);
        int hh = np >> 2, g = np & 3;
        g_ew4[j] = ewh[(g * H + hh) * H + k];
    }
    if (i < H4) {
        int hh = i >> 2, g = i & 3;
        g_eb4[i]  = eb[g * H + hh];
        g_ewi4[i] = ewi[g * H + hh];
    }
}

// g_wcomb rows: 0..511 = w2 ; 512..2559 = dec Wh, gate-interleaved (n' = 4h+g)
__global__ void k_repack_comb(const float* __restrict__ w2,
                              const float* __restrict__ dwh) {
    int i = blockIdx.x * blockDim.x + threadIdx.x;
    int stride = gridDim.x * blockDim.x;
    for (int j = i; j < NC * H; j += stride) {
        int n = j >> 9;
        int k = j & (H - 1);
        float v;
        if (n < H) {
            v = w2[n * H + k];
        } else {
            int np = n - H;
            int hh = np >> 2, g = np & 3;
            v = dwh[(g * H + hh) * H + k];
        }
        g_wcomb[j] = v;
    }
}

// g_dwic rows: dec Wi ctx-part (first 512 cols of [2048 x 513]), gate-interleaved
__global__ void k_repack_dwic(const float* __restrict__ dwi,
                              const float* __restrict__ db) {
    int i = blockIdx.x * blockDim.x + threadIdx.x;
    int stride = gridDim.x * blockDim.x;
    for (int j = i; j < H4 * H; j += stride) {
        int np = j >> 9;
        int k  = j & (H - 1);
        int hh = np >> 2, g = np & 3;
        g_dwic[j] = dwi[(g * H + hh) * (H + 1) + k];
    }
    if (i < H4) {
        int hh = i >> 2, g = i & 3;
        g_db4[i]  = db[g * H + hh];
        g_dwi4[i] = dwi[(g * H + hh) * (H + 1) + H];
    }
}

// ---------------- generic split-K GEMM (R2/R8 core, proven, UNCHANGED) ----------------
// part[kz] = A @ W^T over K-chunk. C is [256 x N], N = gridDim.x*64. A row stride 512.
template <int KTOT, int KS>
__global__ void __launch_bounds__(256) k_gemm(
    const float* __restrict__ W,    // [N x KTOT]
    const float* __restrict__ A0,
    float* __restrict__ part)       // [KS][256][N]
{
    constexpr int KC = KTOT / KS;
    constexpr int NT = KC / 16;

    __shared__ float As[2][16][68];
    __shared__ float Bs[2][16][68];

    const int tid = threadIdx.x;
    const int tx  = tid & 15;
    const int ty  = tid >> 4;
    const int n0  = blockIdx.x * 64;
    const int m0  = blockIdx.y * 64;
    const int kbase = blockIdx.z * KC;
    const int N   = gridDim.x * 64;

    const int rl = tid >> 2;
    const int kl = (tid & 3) * 4;

    float acc[4][4] = {};

    auto gload = [&](int k0, float4& av, float4& wv) {
        const int k = k0 + kl;
        av = *(const float4*)&A0[(m0 + rl) * 512 + k];
        wv = *(const float4*)&W[(size_t)(n0 + rl) * KTOT + k];
    };
    auto sstore = [&](int buf, float4 av, float4 wv) {
        As[buf][kl + 0][rl] = av.x; As[buf][kl + 1][rl] = av.y;
        As[buf][kl + 2][rl] = av.z; As[buf][kl + 3][rl] = av.w;
        Bs[buf][kl + 0][rl] = wv.x; Bs[buf][kl + 1][rl] = wv.y;
        Bs[buf][kl + 2][rl] = wv.z; Bs[buf][kl + 3][rl] = wv.w;
    };

    {
        float4 av, wv;
        gload(kbase, av, wv);
        sstore(0, av, wv);
    }
    __syncthreads();

    for (int t = 0; t < NT; t++) {
        float4 av, wv;
        const bool more = (t + 1 < NT);
        if (more) gload(kbase + (t + 1) * 16, av, wv);

        const int cb = t & 1;
#pragma unroll
        for (int k = 0; k < 16; k++) {
            float4 a = *(const float4*)&As[cb][k][ty * 4];
            float4 b = *(const float4*)&Bs[cb][k][tx * 4];
            acc[0][0] += a.x * b.x; acc[0][1] += a.x * b.y; acc[0][2] += a.x * b.z; acc[0][3] += a.x * b.w;
            acc[1][0] += a.y * b.x; acc[1][1] += a.y * b.y; acc[1][2] += a.y * b.z; acc[1][3] += a.y * b.w;
            acc[2][0] += a.z * b.x; acc[2][1] += a.z * b.y; acc[2][2] += a.z * b.z; acc[2][3] += a.z * b.w;
            acc[3][0] += a.w * b.x; acc[3][1] += a.w * b.y; acc[3][2] += a.w * b.z; acc[3][3] += a.w * b.w;
        }
        if (more) sstore(cb ^ 1, av, wv);
        __syncthreads();
    }

    float* dst = part + (size_t)blockIdx.z * 256 * N;
#pragma unroll
    for (int i = 0; i < 4; i++) {
        float4 o = make_float4(acc[i][0], acc[i][1], acc[i][2], acc[i][3]);
        *(float4*)&dst[(size_t)(m0 + ty * 4 + i) * N + n0 + tx * 4] = o;
    }
}

// ---------------- same core + last-CTA gate fixup (LSTM cell update inline) ----------------
// KTOT=512, KS=2, N=2048. EPI: 0 = encoder, 1 = decoder (adds g_cpart h-half partials).
// After writing its partial, the last-arriving CTA per (x,y) tile reduces partials,
// applies the LSTM cell update for its 16 h x 64 b region, and handles teacher forcing.
template <int EPI>
__global__ void __launch_bounds__(256) k_gemm_fix(
    const float* __restrict__ W,      // [2048 x 512] gate-interleaved rows
    const float* __restrict__ A0,     // enc: h_t ; dec: ctx
    const float* __restrict__ bias4,
    const float* __restrict__ wiv4,
    const int*   __restrict__ xs,
    const int*   __restrict__ argsort,
    int t)
{
    constexpr int KS = 2;
    constexpr int NT = 256 / 16;

    __shared__ float As[2][16][68];
    __shared__ float Bs[2][16][68];
    __shared__ int s_flag;

    const int tid = threadIdx.x;
    const int tx  = tid & 15;
    const int ty  = tid >> 4;
    const int n0  = blockIdx.x * 64;
    const int m0  = blockIdx.y * 64;
    const int kbase = blockIdx.z * 256;
    const int p   = t & 1;

    const int rl = tid >> 2;
    const int kl = (tid & 3) * 4;

    float acc[4][4] = {};

    auto gload = [&](int k0, float4& av, float4& wv) {
        const int k = k0 + kl;
        av = *(const float4*)&A0[(m0 + rl) * 512 + k];
        wv = *(const float4*)&W[(size_t)(n0 + rl) * 512 + k];
    };
    auto sstore = [&](int buf, float4 av, float4 wv) {
        As[buf][kl + 0][rl] = av.x; As[buf][kl + 1][rl] = av.y;
        As[buf][kl + 2][rl] = av.z; As[buf][kl + 3][rl] = av.w;
        Bs[buf][kl + 0][rl] = wv.x; Bs[buf][kl + 1][rl] = wv.y;
        Bs[buf][kl + 2][rl] = wv.z; Bs[buf][kl + 3][rl] = wv.w;
    };

    {
        float4 av, wv;
        gload(kbase, av, wv);
        sstore(0, av, wv);
    }
    __syncthreads();

    for (int it = 0; it < NT; it++) {
        float4 av, wv;
        const bool more = (it + 1 < NT);
        if (more) gload(kbase + (it + 1) * 16, av, wv);

        const int cb = it & 1;
#pragma unroll
        for (int k = 0; k < 16; k++) {
            float4 a = *(const float4*)&As[cb][k][ty * 4];
            float4 b = *(const float4*)&Bs[cb][k][tx * 4];
            acc[0][0] += a.x * b.x; acc[0][1] += a.x * b.y; acc[0][2] += a.x * b.z; acc[0][3] += a.x * b.w;
            acc[1][0] += a.y * b.x; acc[1][1] += a.y * b.y; acc[1][2] += a.y * b.z; acc[1][3] += a.y * b.w;
            acc[2][0] += a.z * b.x; acc[2][1] += a.z * b.y; acc[2][2] += a.z * b.z; acc[2][3] += a.z * b.w;
            acc[3][0] += a.w * b.x; acc[3][1] += a.w * b.y; acc[3][2] += a.w * b.z; acc[3][3] += a.w * b.w;
        }
        if (more) sstore(cb ^ 1, av, wv);
        __syncthreads();
    }

    // write partial
    {
        float* dst = g_zpart + (size_t)blockIdx.z * (B * H4);
#pragma unroll
        for (int i = 0; i < 4; i++) {
            float4 o = make_float4(acc[i][0], acc[i][1], acc[i][2], acc[i][3]);
            *(float4*)&dst[(size_t)(m0 + ty * 4 + i) * H4 + n0 + tx * 4] = o;
        }
    }

    // last-CTA-per-tile election
    __threadfence();
    __syncthreads();
    const int tile = blockIdx.y * gridDim.x + blockIdx.x;
    if (tid == 0) {
        int c = atomicAdd(&g_cnt[tile], 1);
        s_flag = (c == KS - 1) ? 1 : 0;
    }
    __syncthreads();
    if (!s_flag) return;
    if (tid == 0) g_cnt[tile] = 0;
    __threadfence();

    // fixup: 16 h x 64 b region -> 1024 (b,h) updates, 4 per thread
#pragma unroll 1
    for (int r = 0; r < 4; r++) {
        const int id = (r << 8) + tid;
        const int bl = id >> 4;            // 0..63
        const int hl = id & 15;            // 0..15
        const int b  = m0 + bl;
        const int np = n0 + (hl << 2);

        float4 z0 = *(const float4*)&g_zpart[(size_t)b * H4 + np];
        float4 z1 = *(const float4*)&g_zpart[(size_t)(B * H4) + (size_t)b * H4 + np];
        float zx = z0.x + z1.x, zy = z0.y + z1.y, zz = z0.z + z1.z, zw = z0.w + z1.w;
        if (EPI == 1) {
            float4 c0 = *(const float4*)&g_cpart[(size_t)b * NC + 512 + np];
            float4 c1 = *(const float4*)&g_cpart[(size_t)(B * NC) + (size_t)b * NC + 512 + np];
            zx += c0.x + c1.x; zy += c0.y + c1.y; zz += c0.z + c1.z; zw += c0.w + c1.w;
        }
        const float4 bb = *(const float4*)&bias4[np];
        const float4 ww = *(const float4*)&wiv4[np];
        const float xb = (EPI == 0) ? (float)xs[b * L + t] : g_dec_in[p][b];

        const float zi = zx + bb.x + xb * ww.x;
        const float zf = zy + bb.y + xb * ww.y;
        const float zg = zz + bb.z + xb * ww.z;
        const float zo = zw + bb.w + xb * ww.w;

        const int h  = (n0 >> 2) + hl;
        const int ci = b * H + h;
        const float c  = sigmoid_acc(zf) * g_c[ci] + sigmoid_acc(zi) * tanh_acc(zg);
        const float hn = sigmoid_acc(zo) * tanh_acc(c);
        g_c[ci] = c;
        g_h[p ^ 1][ci] = hn;
        if (EPI == 0) {
            const size_t eo = ((size_t)b * L + t) * H + h;
            g_enc_out[eo]  = hn;
            g_enc_outh[eo] = __float2bfloat16_rn(hn);
        } else {
            if (blockIdx.x == 0 && hl == 0) {
                g_dec_in[p ^ 1][b] = (float)xs[b * L + argsort[b * L + t]];
            }
        }
    }
}

// ---------------- enc_w1 = enc_out @ w1^T -> bf16  (M=32768, N=512, K=512) ----------------
__global__ void __launch_bounds__(256) k_encw1(const float* __restrict__ w1) {
    __shared__ float As[16][68];
    __shared__ float Bs[16][68];

    const int tid = threadIdx.x;
    const int tx = tid & 15;
    const int ty = tid >> 4;
    const int n0 = blockIdx.x * 64;
    const int m0 = blockIdx.y * 64;

    const int rl = tid >> 2;
    const int kl = (tid & 3) * 4;

    float acc[4][4] = {};

    for (int k0 = 0; k0 < H; k0 += 16) {
        __syncthreads();
        {
            float4 av = *(const float4*)&g_enc_out[(size_t)(m0 + rl) * H + k0 + kl];
            As[kl + 0][rl] = av.x; As[kl + 1][rl] = av.y;
            As[kl + 2][rl] = av.z; As[kl + 3][rl] = av.w;
            float4 bv = *(const float4*)&w1[(n0 + rl) * H + k0 + kl];
            Bs[kl + 0][rl] = bv.x; Bs[kl + 1][rl] = bv.y;
            Bs[kl + 2][rl] = bv.z; Bs[kl + 3][rl] = bv.w;
        }
        __syncthreads();
#pragma unroll
        for (int k = 0; k < 16; k++) {
            float4 a = *(const float4*)&As[k][ty * 4];
            float4 w = *(const float4*)&Bs[k][tx * 4];
            acc[0][0] += a.x * w.x; acc[0][1] += a.x * w.y; acc[0][2] += a.x * w.z; acc[0][3] += a.x * w.w;
            acc[1][0] += a.y * w.x; acc[1][1] += a.y * w.y; acc[1][2] += a.y * w.z; acc[1][3] += a.y * w.w;
            acc[2][0] += a.z * w.x; acc[2][1] += a.z * w.y; acc[2][2] += a.z * w.z; acc[2][3] += a.z * w.w;
            acc[3][0] += a.w * w.x; acc[3][1] += a.w * w.y; acc[3][2] += a.w * w.z; acc[3][3] += a.w * w.w;
        }
    }
#pragma unroll
    for (int i = 0; i < 4; i++) {
        __nv_bfloat162 p0 = __floats2bfloat162_rn(acc[i][0], acc[i][1]);
        __nv_bfloat162 p1 = __floats2bfloat162_rn(acc[i][2], acc[i][3]);
        uint2 pk = make_uint2(*(unsigned*)&p0, *(unsigned*)&p1);
        *(uint2*)&g_enc_w1h[(size_t)(m0 + ty * 4 + i) * H + n0 + tx * 4] = pk;
    }
}

// ---------------- attention: q-reduce (from cpart) + scores + softmax + context ------------
__global__ void __launch_bounds__(256) k_attn(const float* __restrict__ vt,
                                              float* __restrict__ out, int t) {
    __shared__ float q_s[H];
    __shared__ float vt_s[H];
    __shared__ float sc[L];
    __shared__ float aj[L];

    const int b = blockIdx.x;
    const int tid = threadIdx.x;
    const int lane = tid & 31;
    const int w = tid >> 5;

    for (int i = tid; i < H; i += 256) {
        q_s[i] = g_cpart[(size_t)b * NC + i] +
                 g_cpart[(size_t)(B * NC) + (size_t)b * NC + i];
        vt_s[i] = vt[i];
    }
    __syncthreads();

#pragma unroll 1
    for (int li = 0; li < 16; li++) {
        const int l = w * 16 + li;
        const uint4* e8 = (const uint4*)(g_enc_w1h + (size_t)(b * L + l) * H);
        float s = 0.f;
#pragma unroll
        for (int j = 0; j < 2; j++) {
            const int base = (lane + j * 32) * 8;
            uint4 u = e8[lane + j * 32];
            float4 q0 = *(const float4*)&q_s[base];
            float4 q1 = *(const float4*)&q_s[base + 4];
            float4 v0 = *(const float4*)&vt_s[base];
            float4 v1 = *(const float4*)&vt_s[base + 4];
            float2 e0 = __bfloat1622float2(*(__nv_bfloat162*)&u.x);
            float2 e1 = __bfloat1622float2(*(__nv_bfloat162*)&u.y);
            float2 e2 = __bfloat1622float2(*(__nv_bfloat162*)&u.z);
            float2 e3 = __bfloat1622float2(*(__nv_bfloat162*)&u.w);
            s += v0.x * tanh_fast(e0.x + q0.x);
            s += v0.y * tanh_fast(e0.y + q0.y);
            s += v0.z * tanh_fast(e1.x + q0.z);
            s += v0.w * tanh_fast(e1.y + q0.w);
            s += v1.x * tanh_fast(e2.x + q1.x);
            s += v1.y * tanh_fast(e2.y + q1.y);
            s += v1.z * tanh_fast(e3.x + q1.z);
            s += v1.w * tanh_fast(e3.y + q1.w);
        }
#pragma unroll
        for (int o = 16; o > 0; o >>= 1) s += __shfl_xor_sync(0xffffffffu, s, o);
        if (lane == 0) sc[l] = s;
    }
    __syncthreads();

    if (w == 0) {
        float sv[4];
        float m = -1e30f;
#pragma unroll
        for (int k = 0; k < 4; k++) { sv[k] = sc[lane * 4 + k]; m = fmaxf(m, sv[k]); }
#pragma unroll
        for (int o = 16; o > 0; o >>= 1) m = fmaxf(m, __shfl_xor_sync(0xffffffffu, m, o));
        float e[4], sum = 0.f;
#pragma unroll
        for (int k = 0; k < 4; k++) { e[k] = __expf(sv[k] - m); sum += e[k]; }
#pragma unroll
        for (int o = 16; o > 0; o >>= 1) sum += __shfl_xor_sync(0xffffffffu, sum, o);
        const float ls  = __logf(sum);
        const float inv = 1.0f / sum;
        float* orow = out + ((size_t)b * L + t) * L;
#pragma unroll
        for (int k = 0; k < 4; k++) {
            orow[lane * 4 + k] = sv[k] - m - ls;
            aj[lane * 4 + k]   = e[k] * inv;
        }
    }
    __syncthreads();

    const int h2 = tid * 2;
    float ax = 0.f, ay = 0.f;
    const __nv_bfloat162* base =
        (const __nv_bfloat162*)(g_enc_outh + (size_t)b * L * H + h2);
#pragma unroll 4
    for (int l = 0; l < L; l++) {
        const float a = aj[l];
        float2 v = __bfloat1622float2(base[(size_t)l * (H / 2)]);
        ax += a * v.x;
        ay += a * v.y;
    }
    g_ctx[b * H + h2]     = ax;
    g_ctx[b * H + h2 + 1] = ay;
}

}  // namespace

extern "C" void kernel_launch(void* const* d_in, const int* in_sizes, int n_in,
                              void* d_out, int out_size) {
    (void)in_sizes; (void)n_in; (void)out_size;
    const int*   xs      = (const int*)d_in[0];
    const int*   argsort = (const int*)d_in[2];
    const float* enc_Wi  = (const float*)d_in[3];
    const float* enc_Wh  = (const float*)d_in[4];
    const float* enc_b   = (const float*)d_in[5];
    const float* dec_Wi  = (const float*)d_in[6];
    const float* dec_Wh  = (const float*)d_in[7];
    const float* dec_b   = (const float*)d_in[8];
    const float* w1      = (const float*)d_in[9];
    const float* w2      = (const float*)d_in[10];
    const float* vt      = (const float*)d_in[11];
    float* out = (float*)d_out;

    float *p_h, *p_ctx, *p_ew4, *p_eb4, *p_ewi4, *p_wcomb, *p_dwic, *p_db4, *p_dwi4, *p_cpart;
    cudaGetSymbolAddress((void**)&p_h,     g_h);
    cudaGetSymbolAddress((void**)&p_ctx,   g_ctx);
    cudaGetSymbolAddress((void**)&p_ew4,   g_ew4);
    cudaGetSymbolAddress((void**)&p_eb4,   g_eb4);
    cudaGetSymbolAddress((void**)&p_ewi4,  g_ewi4);
    cudaGetSymbolAddress((void**)&p_wcomb, g_wcomb);
    cudaGetSymbolAddress((void**)&p_dwic,  g_dwic);
    cudaGetSymbolAddress((void**)&p_db4,   g_db4);
    cudaGetSymbolAddress((void**)&p_dwi4,  g_dwi4);
    cudaGetSymbolAddress((void**)&p_cpart, g_cpart);

    k_init<<<128, 256>>>();
    k_repack_enc<<<256, 256>>>(enc_Wh, enc_b, enc_Wi);
    k_repack_comb<<<512, 256>>>(w2, dec_Wh);
    k_repack_dwic<<<256, 256>>>(dec_Wi, dec_b);

    const dim3 lstm_grid(H4 / 64, B / 64, 2);       // (32, 4, 2) = 256 CTAs
    const dim3 comb_grid(NC / 64, B / 64, 2);       // (40, 4, 2) = 320 CTAs
    const dim3 encw1_grid(H / 64, (B * L) / 64);    // (8, 512)

    // ---- encoder: 128 steps, ONE launch each (GEMM + inline gate fixup) ----
    for (int t = 0; t < L; t++) {
        const float* hp = p_h + (size_t)(t & 1) * (B * H);
        k_gemm_fix<0><<<lstm_grid, 256>>>(p_ew4, hp, p_eb4, p_ewi4, xs, nullptr, t);
    }

    // ---- hoisted projection enc_w1 = enc_out @ w1^T (bf16 out) ----
    k_encw1<<<encw1_grid, 256>>>(w1);

    // ---- decoder: 128 steps of [q|zh] combined GEMM -> attention -> ctx GEMM + fixup ----
    for (int t = 0; t < L; t++) {
        const float* hp = p_h + (size_t)(t & 1) * (B * H);
        k_gemm<512, 2><<<comb_grid, 256>>>(p_wcomb, hp, p_cpart);
        k_attn<<<B, 256>>>(vt, out, t);
        k_gemm_fix<1><<<lstm_grid, 256>>>(p_dwic, p_ctx, p_db4, p_dwi4, xs, argsort, t);
    }
}

// round 10
// speedup vs baseline: 1.2253x; 1.2253x over previous
#include <cuda_runtime.h>
#include <cuda_bf16.h>
#include <math.h>

namespace {

constexpr int B  = 256;
constexpr int L  = 128;
constexpr int H  = 512;
constexpr int H4 = 2048;

// ---------------- device state (allocation-free scratch) ----------------
__device__ float g_h[2][B * H];                          // hidden, double buffered by parity
__device__ float g_c[B * H];                             // cell
__device__ float g_enc_out[(size_t)B * L * H];           // fp32 [b*L+l][h] (encw1 A input)
__device__ __nv_bfloat16 g_enc_outh[(size_t)B * L * H];  // bf16 [b][l][h] (attn context)
__device__ __nv_bfloat16 g_enc_w1h[(size_t)B * L * H];   // bf16 [b*L+l][h] (attn scores)
__device__ float g_ctx[B * H];                           // attention context
__device__ float g_dec_in[2][B];                         // decoder scalar input
__device__ float g_ew4[H4 * H];                          // enc_Wh, gate-interleaved rows n'=4h+g
__device__ float g_eb4[H4];                              // enc bias, interleaved
__device__ float g_ewi4[H4];                             // enc Wi (scalar input), interleaved
__device__ float g_dw4[H4 * 1024];                       // dec [Wi(ctx)|Wh], interleaved, stride 1024
__device__ float g_db4[H4];
__device__ float g_dwi4[H4];                             // dec Wi last column, interleaved
__device__ float g_zpart[2 * B * H4];                    // split-K partials, [kz][b][n'=4h+g]
__device__ float g_qpart[8 * B * H];                     // split-K partials for q

// ---------------- math helpers ----------------
__device__ __forceinline__ float sigmoid_acc(float x) {
    return 1.0f / (1.0f + __expf(-x));
}
__device__ __forceinline__ float tanh_acc(float x) {
    float e = __expf(-2.0f * fabsf(x));
    float r = (1.0f - e) / (1.0f + e);
    return copysignf(r, x);
}
__device__ __forceinline__ float tanh_fast(float x) {
    float y;
    asm("tanh.approx.f32 %0, %1;" : "=f"(y) : "f"(x));
    return y;
}
__device__ __forceinline__ unsigned tf32u(float x) {
    unsigned r;
    asm("cvt.rna.tf32.f32 %0, %1;" : "=r"(r) : "f"(x));
    return r;
}
__device__ __forceinline__ void mma_tf32(float c[4], const unsigned a[4], const unsigned b[2]) {
    asm("mma.sync.aligned.m16n8k8.row.col.f32.tf32.tf32.f32 "
        "{%0,%1,%2,%3},{%4,%5,%6,%7},{%8,%9},{%0,%1,%2,%3};"
        : "+f"(c[0]), "+f"(c[1]), "+f"(c[2]), "+f"(c[3])
        : "r"(a[0]), "r"(a[1]), "r"(a[2]), "r"(a[3]), "r"(b[0]), "r"(b[1]));
}

// ---------------- init ----------------
__global__ void k_init() {
    int i = blockIdx.x * blockDim.x + threadIdx.x;
    int stride = gridDim.x * blockDim.x;
    for (int j = i; j < B * H; j += stride) {
        g_h[0][j] = 0.0f;
        g_c[j]    = 0.0f;
    }
    if (i < B) g_dec_in[0][i] = 0.0f;
}

// ---------------- one-time repacks: gate-interleave rows (n' = 4h + g) ----------------
__global__ void k_repack_enc(const float* __restrict__ ewh,
                             const float* __restrict__ eb,
                             const float* __restrict__ ewi) {
    int i = blockIdx.x * blockDim.x + threadIdx.x;
    int stride = gridDim.x * blockDim.x;
    for (int j = i; j < H4 * H; j += stride) {
        int np = j >> 9;
        int k  = j & (H - 1);
        int hh = np >> 2, g = np & 3;
        g_ew4[j] = ewh[(g * H + hh) * H + k];
    }
    if (i < H4) {
        int hh = i >> 2, g = i & 3;
        g_eb4[i]  = eb[g * H + hh];
        g_ewi4[i] = ewi[g * H + hh];
    }
}

__global__ void k_repack_dec(const float* __restrict__ dwi,
                             const float* __restrict__ dwh,
                             const float* __restrict__ db) {
    int i = blockIdx.x * blockDim.x + threadIdx.x;
    int stride = gridDim.x * blockDim.x;
    for (int j = i; j < H4 * 1024; j += stride) {
        int np = j >> 10;
        int k  = j & 1023;
        int hh = np >> 2, g = np & 3;
        int row = g * H + hh;
        g_dw4[j] = (k < H) ? dwi[row * (H + 1) + k] : dwh[row * H + (k - H)];
    }
    if (i < H4) {
        int hh = i >> 2, g = i & 3;
        g_db4[i]  = db[g * H + hh];
        g_dwi4[i] = dwi[(g * H + hh) * (H + 1) + H];
    }
}

// ======================================================================================
// tf32 tensor-core GEMM: part[kz] = A @ W^T over K-chunk (or bf16 direct store).
// CTA: 128 threads = 4 warps in 2x2, tile 64m x 64n; warp tile 32x32 via m16n8k8 mma.
// Double-buffered smem (As[m][k], Bs[n][k], pad 20 -> conflict-free fragment loads).
// A rows have stride 512 (CONCAT: k<512 from A0, else A1). EPI: 0 = fp32 partials,
// 1 = bf16 store to g_enc_w1h.
// ======================================================================================
template <int KTOT, int KS, bool CONCAT, int EPI>
__global__ void __launch_bounds__(128) k_mma(
    const float* __restrict__ W,     // [N x KTOT]
    const float* __restrict__ A0,
    const float* __restrict__ A1,
    float* __restrict__ part)        // [KS][256][N]
{
    constexpr int KC  = KTOT / KS;
    constexpr int NST = KC / 16;

    __shared__ unsigned As[2][64][20];
    __shared__ unsigned Bs[2][64][20];

    const int tid  = threadIdx.x;
    const int warp = tid >> 5;
    const int lane = tid & 31;
    const int mw   = (warp >> 1) * 32;
    const int nw   = (warp & 1) * 32;
    const int n0   = blockIdx.x * 64;
    const int m0   = blockIdx.y * 64;
    const int kb   = blockIdx.z * KC;
    const int N    = gridDim.x * 64;

    const int lr = tid >> 2;          // 0..31 (row within tile, +32 for second half)
    const int lk = (tid & 3) * 4;     // 0,4,8,12

    float c[2][4][4] = {};

    unsigned a_r[2][4], w_r[2][4];
    auto gload = [&](int k0) {
#pragma unroll
        for (int hh = 0; hh < 2; hh++) {
            const int row = lr + hh * 32;
            const int k = kb + k0 + lk;
            const float* ap;
            if (CONCAT) {
                ap = (k < 512) ? &A0[(m0 + row) * 512 + k]
                               : &A1[(m0 + row) * 512 + (k - 512)];
            } else {
                ap = &A0[(size_t)(m0 + row) * 512 + k];
            }
            float4 av = *(const float4*)ap;
            float4 wv = *(const float4*)&W[(size_t)(n0 + row) * KTOT + k];
            a_r[hh][0] = tf32u(av.x); a_r[hh][1] = tf32u(av.y);
            a_r[hh][2] = tf32u(av.z); a_r[hh][3] = tf32u(av.w);
            w_r[hh][0] = tf32u(wv.x); w_r[hh][1] = tf32u(wv.y);
            w_r[hh][2] = tf32u(wv.z); w_r[hh][3] = tf32u(wv.w);
        }
    };
    auto sstore = [&](int buf) {
#pragma unroll
        for (int hh = 0; hh < 2; hh++) {
            const int row = lr + hh * 32;
#pragma unroll
            for (int i = 0; i < 4; i++) {
                As[buf][row][lk + i] = a_r[hh][i];
                Bs[buf][row][lk + i] = w_r[hh][i];
            }
        }
    };

    gload(0);
    sstore(0);
    __syncthreads();

    for (int st = 0; st < NST; st++) {
        const bool more = (st + 1 < NST);
        if (more) gload((st + 1) * 16);

        const int cb = st & 1;
#pragma unroll
        for (int k8 = 0; k8 < 16; k8 += 8) {
            unsigned af[2][4], bfr[4][2];
            const int kk = k8 + (lane & 3);
            const int rq = lane >> 2;
#pragma unroll
            for (int mt = 0; mt < 2; mt++) {
                const int r = mw + mt * 16 + rq;
                af[mt][0] = As[cb][r][kk];
                af[mt][1] = As[cb][r + 8][kk];
                af[mt][2] = As[cb][r][kk + 4];
                af[mt][3] = As[cb][r + 8][kk + 4];
            }
#pragma unroll
            for (int nt = 0; nt < 4; nt++) {
                const int nc = nw + nt * 8 + rq;
                bfr[nt][0] = Bs[cb][nc][kk];
                bfr[nt][1] = Bs[cb][nc][kk + 4];
            }
#pragma unroll
            for (int mt = 0; mt < 2; mt++)
#pragma unroll
                for (int nt = 0; nt < 4; nt++)
                    mma_tf32(c[mt][nt], af[mt], bfr[nt]);
        }
        if (more) sstore(cb ^ 1);
        __syncthreads();
    }

    // ---------------- epilogue ----------------
#pragma unroll
    for (int mt = 0; mt < 2; mt++) {
#pragma unroll
        for (int nt = 0; nt < 4; nt++) {
            const int m = m0 + mw + mt * 16 + (lane >> 2);
            const int n = n0 + nw + nt * 8 + ((lane & 3) << 1);
            if (EPI == 0) {
                float* dst = part + (size_t)blockIdx.z * 256 * N;
                *(float2*)&dst[(size_t)m * N + n]       = make_float2(c[mt][nt][0], c[mt][nt][1]);
                *(float2*)&dst[(size_t)(m + 8) * N + n] = make_float2(c[mt][nt][2], c[mt][nt][3]);
            } else {
                __nv_bfloat162 p0 = __floats2bfloat162_rn(c[mt][nt][0], c[mt][nt][1]);
                __nv_bfloat162 p1 = __floats2bfloat162_rn(c[mt][nt][2], c[mt][nt][3]);
                *(unsigned*)&g_enc_w1h[(size_t)m * H + n]       = *(unsigned*)&p0;
                *(unsigned*)&g_enc_w1h[(size_t)(m + 8) * H + n] = *(unsigned*)&p1;
            }
        }
    }
}

// ---------------- gates (R8, proven): coalesced float4 partial reduce + cell update -------
template <bool DEC>
__global__ void __launch_bounds__(256) k_gates(
    const float* __restrict__ bias4,
    const float* __restrict__ wiv4,
    const int*   __restrict__ xs,
    const int*   __restrict__ argsort,
    int t)
{
    const int idx = blockIdx.x * 256 + threadIdx.x;
    const int b = idx >> 9;
    const int h = idx & (H - 1);
    const int np = h << 2;
    const int p = t & 1;

    const float xb = DEC ? g_dec_in[p][b] : (float)xs[b * L + t];

    float4 z0 = *(const float4*)&g_zpart[(size_t)b * H4 + np];
    float4 z1 = *(const float4*)&g_zpart[(size_t)(B * H4) + (size_t)b * H4 + np];
    const float4 bb = *(const float4*)&bias4[np];
    const float4 ww = *(const float4*)&wiv4[np];

    const float zi = z0.x + z1.x + bb.x + xb * ww.x;
    const float zf = z0.y + z1.y + bb.y + xb * ww.y;
    const float zg = z0.z + z1.z + bb.z + xb * ww.z;
    const float zo = z0.w + z1.w + bb.w + xb * ww.w;

    const float c  = sigmoid_acc(zf) * g_c[idx] + sigmoid_acc(zi) * tanh_acc(zg);
    const float hn = sigmoid_acc(zo) * tanh_acc(c);
    g_c[idx] = c;
    g_h[p ^ 1][idx] = hn;
    if (!DEC) {
        const size_t eo = ((size_t)b * L + t) * H + h;
        g_enc_out[eo]  = hn;
        g_enc_outh[eo] = __float2bfloat16_rn(hn);
    }
    if (DEC && h == 0) {
        g_dec_in[p ^ 1][b] = (float)xs[b * L + argsort[b * L + t]];
    }
}

// ---------------- attention (R8, proven): q-reduce + scores + softmax + context -----------
__global__ void __launch_bounds__(256) k_attn(const float* __restrict__ vt,
                                              float* __restrict__ out, int t) {
    __shared__ float q_s[H];
    __shared__ float vt_s[H];
    __shared__ float sc[L];
    __shared__ float aj[L];

    const int b = blockIdx.x;
    const int tid = threadIdx.x;
    const int lane = tid & 31;
    const int w = tid >> 5;

    for (int i = tid; i < H; i += 256) {
        float s = 0.0f;
#pragma unroll
        for (int sp = 0; sp < 8; sp++)
            s += g_qpart[(size_t)sp * (B * H) + b * H + i];
        q_s[i]  = s;
        vt_s[i] = vt[i];
    }
    __syncthreads();

#pragma unroll 1
    for (int li = 0; li < 16; li++) {
        const int l = w * 16 + li;
        const uint4* e8 = (const uint4*)(g_enc_w1h + (size_t)(b * L + l) * H);
        float s = 0.f;
#pragma unroll
        for (int j = 0; j < 2; j++) {
            const int base = (lane + j * 32) * 8;
            uint4 u = e8[lane + j * 32];
            float4 q0 = *(const float4*)&q_s[base];
            float4 q1 = *(const float4*)&q_s[base + 4];
            float4 v0 = *(const float4*)&vt_s[base];
            float4 v1 = *(const float4*)&vt_s[base + 4];
            float2 e0 = __bfloat1622float2(*(__nv_bfloat162*)&u.x);
            float2 e1 = __bfloat1622float2(*(__nv_bfloat162*)&u.y);
            float2 e2 = __bfloat1622float2(*(__nv_bfloat162*)&u.z);
            float2 e3 = __bfloat1622float2(*(__nv_bfloat162*)&u.w);
            s += v0.x * tanh_fast(e0.x + q0.x);
            s += v0.y * tanh_fast(e0.y + q0.y);
            s += v0.z * tanh_fast(e1.x + q0.z);
            s += v0.w * tanh_fast(e1.y + q0.w);
            s += v1.x * tanh_fast(e2.x + q1.x);
            s += v1.y * tanh_fast(e2.y + q1.y);
            s += v1.z * tanh_fast(e3.x + q1.z);
            s += v1.w * tanh_fast(e3.y + q1.w);
        }
#pragma unroll
        for (int o = 16; o > 0; o >>= 1) s += __shfl_xor_sync(0xffffffffu, s, o);
        if (lane == 0) sc[l] = s;
    }
    __syncthreads();

    if (w == 0) {
        float sv[4];
        float m = -1e30f;
#pragma unroll
        for (int k = 0; k < 4; k++) { sv[k] = sc[lane * 4 + k]; m = fmaxf(m, sv[k]); }
#pragma unroll
        for (int o = 16; o > 0; o >>= 1) m = fmaxf(m, __shfl_xor_sync(0xffffffffu, m, o));
        float e[4], sum = 0.f;
#pragma unroll
        for (int k = 0; k < 4; k++) { e[k] = __expf(sv[k] - m); sum += e[k]; }
#pragma unroll
        for (int o = 16; o > 0; o >>= 1) sum += __shfl_xor_sync(0xffffffffu, sum, o);
        const float ls  = __logf(sum);
        const float inv = 1.0f / sum;
        float* orow = out + ((size_t)b * L + t) * L;
#pragma unroll
        for (int k = 0; k < 4; k++) {
            orow[lane * 4 + k] = sv[k] - m - ls;
            aj[lane * 4 + k]   = e[k] * inv;
        }
    }
    __syncthreads();

    const int h2 = tid * 2;
    float ax = 0.f, ay = 0.f;
    const __nv_bfloat162* base =
        (const __nv_bfloat162*)(g_enc_outh + (size_t)b * L * H + h2);
#pragma unroll 4
    for (int l = 0; l < L; l++) {
        const float a = aj[l];
        float2 v = __bfloat1622float2(base[(size_t)l * (H / 2)]);
        ax += a * v.x;
        ay += a * v.y;
    }
    g_ctx[b * H + h2]     = ax;
    g_ctx[b * H + h2 + 1] = ay;
}

}  // namespace

extern "C" void kernel_launch(void* const* d_in, const int* in_sizes, int n_in,
                              void* d_out, int out_size) {
    (void)in_sizes; (void)n_in; (void)out_size;
    const int*   xs      = (const int*)d_in[0];
    const int*   argsort = (const int*)d_in[2];
    const float* enc_Wi  = (const float*)d_in[3];
    const float* enc_Wh  = (const float*)d_in[4];
    const float* enc_b   = (const float*)d_in[5];
    const float* dec_Wi  = (const float*)d_in[6];
    const float* dec_Wh  = (const float*)d_in[7];
    const float* dec_b   = (const float*)d_in[8];
    const float* w1      = (const float*)d_in[9];
    const float* w2      = (const float*)d_in[10];
    const float* vt      = (const float*)d_in[11];
    float* out = (float*)d_out;

    float *p_h, *p_ctx, *p_encout, *p_ew4, *p_eb4, *p_ewi4, *p_dw4, *p_db4, *p_dwi4;
    float *p_zpart, *p_qpart;
    cudaGetSymbolAddress((void**)&p_h,      g_h);
    cudaGetSymbolAddress((void**)&p_ctx,    g_ctx);
    cudaGetSymbolAddress((void**)&p_encout, g_enc_out);
    cudaGetSymbolAddress((void**)&p_ew4,    g_ew4);
    cudaGetSymbolAddress((void**)&p_eb4,    g_eb4);
    cudaGetSymbolAddress((void**)&p_ewi4,   g_ewi4);
    cudaGetSymbolAddress((void**)&p_dw4,    g_dw4);
    cudaGetSymbolAddress((void**)&p_db4,    g_db4);
    cudaGetSymbolAddress((void**)&p_dwi4,   g_dwi4);
    cudaGetSymbolAddress((void**)&p_zpart,  g_zpart);
    cudaGetSymbolAddress((void**)&p_qpart,  g_qpart);

    k_init<<<128, 256>>>();
    k_repack_enc<<<256, 256>>>(enc_Wh, enc_b, enc_Wi);
    k_repack_dec<<<512, 256>>>(dec_Wi, dec_Wh, dec_b);

    const dim3 gates_grid(B * H / 256);             // 512
    const dim3 lstm_gemm(H4 / 64, B / 64, 2);       // (32, 4, 2) = 256 CTAs
    const dim3 q_gemm(H / 64, B / 64, 8);           // (8, 4, 8)  = 256 CTAs
    const dim3 encw1_grid(H / 64, (B * L) / 64, 1); // (8, 512)

    // ---- encoder: 128 steps of tf32-mma split-K GEMM + gates ----
    for (int t = 0; t < L; t++) {
        const float* hp = p_h + (size_t)(t & 1) * (B * H);
        k_mma<512, 2, false, 0><<<lstm_gemm, 128>>>(p_ew4, hp, nullptr, p_zpart);
        k_gates<false><<<gates_grid, 256>>>(p_eb4, p_ewi4, xs, nullptr, t);
    }

    // ---- hoisted projection enc_w1 = enc_out @ w1^T (tf32 mma, bf16 out) ----
    k_mma<512, 1, false, 1><<<encw1_grid, 128>>>(w1, p_encout, nullptr, nullptr);

    // ---- decoder: 128 steps of q-proj -> attention -> LSTM GEMM + gates ----
    for (int t = 0; t < L; t++) {
        const float* hp = p_h + (size_t)(t & 1) * (B * H);
        k_mma<512, 8, false, 0><<<q_gemm, 128>>>(w2, hp, nullptr, p_qpart);
        k_attn<<<B, 256>>>(vt, out, t);
        k_mma<1024, 2, true, 0><<<lstm_gemm, 128>>>(p_dw4, p_ctx, hp, p_zpart);
        k_gates<true><<<gates_grid, 256>>>(p_db4, p_dwi4, xs, argsort, t);
    }
}

// round 11
// speedup vs baseline: 1.3572x; 1.1077x over previous
#include <cuda_runtime.h>
#include <cuda_bf16.h>
#include <math.h>

namespace {

constexpr int B  = 256;
constexpr int L  = 128;
constexpr int H  = 512;
constexpr int H4 = 2048;

// ---------------- device state (allocation-free scratch) ----------------
__device__ float g_h[2][B * H];                          // hidden, double buffered by parity
__device__ float g_c[B * H];                             // cell
__device__ float g_enc_out[(size_t)B * L * H];           // fp32 [b*L+l][h] (encw1 A input)
__device__ __nv_bfloat16 g_enc_outh[(size_t)B * L * H];  // bf16 [b][l][h] (attn context)
__device__ __nv_bfloat16 g_enc_w1h[(size_t)B * L * H];   // bf16 [b*L+l][h] (attn scores)
__device__ float g_ctx[B * H];                           // attention context
__device__ float g_dec_in[2][B];                         // decoder scalar input
__device__ float g_ew4[H4 * H];                          // enc_Wh, gate-interleaved rows n'=4h+g
__device__ float g_eb4[H4];                              // enc bias, interleaved
__device__ float g_ewi4[H4];                             // enc Wi (scalar input), interleaved
__device__ float g_dw4[H4 * 1024];                       // dec [Wi(ctx)|Wh], interleaved, stride 1024
__device__ float g_db4[H4];
__device__ float g_dwi4[H4];                             // dec Wi last column, interleaved
__device__ float g_zpart[4 * B * H4];                    // split-K partials, [kz][b][n'=4h+g]
__device__ float g_qpart[8 * B * H];                     // split-K partials for q

// ---------------- math helpers ----------------
__device__ __forceinline__ float sigmoid_acc(float x) {
    return 1.0f / (1.0f + __expf(-x));
}
__device__ __forceinline__ float tanh_acc(float x) {
    float e = __expf(-2.0f * fabsf(x));
    float r = (1.0f - e) / (1.0f + e);
    return copysignf(r, x);
}
__device__ __forceinline__ float tanh_fast(float x) {
    float y;
    asm("tanh.approx.f32 %0, %1;" : "=f"(y) : "f"(x));
    return y;
}
__device__ __forceinline__ unsigned tf32u(float x) {
    unsigned r;
    asm("cvt.rna.tf32.f32 %0, %1;" : "=r"(r) : "f"(x));
    return r;
}
__device__ __forceinline__ void mma_tf32(float c[4], const unsigned a[4], const unsigned b[2]) {
    asm("mma.sync.aligned.m16n8k8.row.col.f32.tf32.tf32.f32 "
        "{%0,%1,%2,%3},{%4,%5,%6,%7},{%8,%9},{%0,%1,%2,%3};"
        : "+f"(c[0]), "+f"(c[1]), "+f"(c[2]), "+f"(c[3])
        : "r"(a[0]), "r"(a[1]), "r"(a[2]), "r"(a[3]), "r"(b[0]), "r"(b[1]));
}

// ---------------- init ----------------
__global__ void k_init() {
    int i = blockIdx.x * blockDim.x + threadIdx.x;
    int stride = gridDim.x * blockDim.x;
    for (int j = i; j < B * H; j += stride) {
        g_h[0][j] = 0.0f;
        g_c[j]    = 0.0f;
    }
    if (i < B) g_dec_in[0][i] = 0.0f;
}

// ---------------- one-time repacks: gate-interleave rows (n' = 4h + g) ----------------
__global__ void k_repack_enc(const float* __restrict__ ewh,
                             const float* __restrict__ eb,
                             const float* __restrict__ ewi) {
    int i = blockIdx.x * blockDim.x + threadIdx.x;
    int stride = gridDim.x * blockDim.x;
    for (int j = i; j < H4 * H; j += stride) {
        int np = j >> 9;
        int k  = j & (H - 1);
        int hh = np >> 2, g = np & 3;
        g_ew4[j] = ewh[(g * H + hh) * H + k];
    }
    if (i < H4) {
        int hh = i >> 2, g = i & 3;
        g_eb4[i]  = eb[g * H + hh];
        g_ewi4[i] = ewi[g * H + hh];
    }
}

__global__ void k_repack_dec(const float* __restrict__ dwi,
                             const float* __restrict__ dwh,
                             const float* __restrict__ db) {
    int i = blockIdx.x * blockDim.x + threadIdx.x;
    int stride = gridDim.x * blockDim.x;
    for (int j = i; j < H4 * 1024; j += stride) {
        int np = j >> 10;
        int k  = j & 1023;
        int hh = np >> 2, g = np & 3;
        int row = g * H + hh;
        g_dw4[j] = (k < H) ? dwi[row * (H + 1) + k] : dwh[row * H + (k - H)];
    }
    if (i < H4) {
        int hh = i >> 2, g = i & 3;
        g_db4[i]  = db[g * H + hh];
        g_dwi4[i] = dwi[(g * H + hh) * (H + 1) + H];
    }
}

// ======================================================================================
// tf32 tensor-core GEMM: part[kz] = A @ W^T over K-chunk (or bf16 direct store).
// CTA: 128 threads = 4 warps in 2x2, tile 64m x 64n; warp tile 32x32 via m16n8k8 mma.
// k-PERMUTED smem layout: element (row, k) lives at column P(k) where P pairs
// (kk, kk+4) adjacently -> every mma fragment pair is one aligned LDS.64.
//   writer (owns k = (tid&3)*4 + i):  column = i*4 + (tid&3)
//   reader (needs kk = k8 + (lane&3)): column = (lane&3)*4 + (k8>>2), pair at +1
// EPI: 0 = fp32 partials, 1 = bf16 store to g_enc_w1h.
// ======================================================================================
template <int KTOT, int KS, bool CONCAT, int EPI>
__global__ void __launch_bounds__(128) k_mma(
    const float* __restrict__ W,     // [N x KTOT]
    const float* __restrict__ A0,
    const float* __restrict__ A1,
    float* __restrict__ part)        // [KS][256][N]
{
    constexpr int KC  = KTOT / KS;
    constexpr int NST = KC / 16;
    constexpr int PAD = 24;

    __shared__ unsigned As[2][64][PAD];
    __shared__ unsigned Bs[2][64][PAD];

    const int tid  = threadIdx.x;
    const int warp = tid >> 5;
    const int lane = tid & 31;
    const int mw   = (warp >> 1) * 32;
    const int nw   = (warp & 1) * 32;
    const int n0   = blockIdx.x * 64;
    const int m0   = blockIdx.y * 64;
    const int kb   = blockIdx.z * KC;
    const int N    = gridDim.x * 64;

    const int lr = tid >> 2;          // 0..31 (row within tile, +32 for second half)
    const int lq = tid & 3;           // k quad owner
    const int lk = lq * 4;

    float c[2][4][4] = {};

    unsigned a_r[2][4], w_r[2][4];
    auto gload = [&](int k0) {
#pragma unroll
        for (int hh = 0; hh < 2; hh++) {
            const int row = lr + hh * 32;
            const int k = kb + k0 + lk;
            const float* ap;
            if (CONCAT) {
                ap = (k < 512) ? &A0[(m0 + row) * 512 + k]
                               : &A1[(m0 + row) * 512 + (k - 512)];
            } else {
                ap = &A0[(size_t)(m0 + row) * 512 + k];
            }
            float4 av = *(const float4*)ap;
            float4 wv = *(const float4*)&W[(size_t)(n0 + row) * KTOT + k];
            a_r[hh][0] = tf32u(av.x); a_r[hh][1] = tf32u(av.y);
            a_r[hh][2] = tf32u(av.z); a_r[hh][3] = tf32u(av.w);
            w_r[hh][0] = tf32u(wv.x); w_r[hh][1] = tf32u(wv.y);
            w_r[hh][2] = tf32u(wv.z); w_r[hh][3] = tf32u(wv.w);
        }
    };
    auto sstore = [&](int buf) {
#pragma unroll
        for (int hh = 0; hh < 2; hh++) {
            const int row = lr + hh * 32;
#pragma unroll
            for (int i = 0; i < 4; i++) {
                const int col = i * 4 + lq;         // P((tid&3)*4 + i)
                As[buf][row][col] = a_r[hh][i];
                Bs[buf][row][col] = w_r[hh][i];
            }
        }
    };

    gload(0);
    sstore(0);
    __syncthreads();

    for (int st = 0; st < NST; st++) {
        const bool more = (st + 1 < NST);
        if (more) gload((st + 1) * 16);

        const int cb = st & 1;
#pragma unroll
        for (int k8 = 0; k8 < 16; k8 += 8) {
            const int cidx = ((lane & 3) << 2) | (k8 >> 2);   // P(k8 + (lane&3)); pair at +1
            const int rq = lane >> 2;
            unsigned af[2][4], bfr[4][2];
#pragma unroll
            for (int mt = 0; mt < 2; mt++) {
                const int r = mw + mt * 16 + rq;
                uint2 lo = *(const uint2*)&As[cb][r][cidx];      // (kk, kk+4) of row r
                uint2 hi = *(const uint2*)&As[cb][r + 8][cidx];  // (kk, kk+4) of row r+8
                af[mt][0] = lo.x; af[mt][1] = hi.x;
                af[mt][2] = lo.y; af[mt][3] = hi.y;
            }
#pragma unroll
            for (int nt = 0; nt < 4; nt++) {
                const int nc = nw + nt * 8 + rq;
                uint2 bb = *(const uint2*)&Bs[cb][nc][cidx];
                bfr[nt][0] = bb.x; bfr[nt][1] = bb.y;
            }
#pragma unroll
            for (int mt = 0; mt < 2; mt++)
#pragma unroll
                for (int nt = 0; nt < 4; nt++)
                    mma_tf32(c[mt][nt], af[mt], bfr[nt]);
        }
        if (more) sstore(cb ^ 1);
        __syncthreads();
    }

    // ---------------- epilogue ----------------
#pragma unroll
    for (int mt = 0; mt < 2; mt++) {
#pragma unroll
        for (int nt = 0; nt < 4; nt++) {
            const int m = m0 + mw + mt * 16 + (lane >> 2);
            const int n = n0 + nw + nt * 8 + ((lane & 3) << 1);
            if (EPI == 0) {
                float* dst = part + (size_t)blockIdx.z * 256 * N;
                *(float2*)&dst[(size_t)m * N + n]       = make_float2(c[mt][nt][0], c[mt][nt][1]);
                *(float2*)&dst[(size_t)(m + 8) * N + n] = make_float2(c[mt][nt][2], c[mt][nt][3]);
            } else {
                __nv_bfloat162 p0 = __floats2bfloat162_rn(c[mt][nt][0], c[mt][nt][1]);
                __nv_bfloat162 p1 = __floats2bfloat162_rn(c[mt][nt][2], c[mt][nt][3]);
                *(unsigned*)&g_enc_w1h[(size_t)m * H + n]       = *(unsigned*)&p0;
                *(unsigned*)&g_enc_w1h[(size_t)(m + 8) * H + n] = *(unsigned*)&p1;
            }
        }
    }
}

// ---------------- gates: coalesced float4 partial reduce (KS=4) + cell update -------------
template <bool DEC>
__global__ void __launch_bounds__(256) k_gates(
    const float* __restrict__ bias4,
    const float* __restrict__ wiv4,
    const int*   __restrict__ xs,
    const int*   __restrict__ argsort,
    int t)
{
    const int idx = blockIdx.x * 256 + threadIdx.x;
    const int b = idx >> 9;
    const int h = idx & (H - 1);
    const int np = h << 2;
    const int p = t & 1;

    const float xb = DEC ? g_dec_in[p][b] : (float)xs[b * L + t];

    float zx = 0.f, zy = 0.f, zz = 0.f, zw = 0.f;
#pragma unroll
    for (int kz = 0; kz < 4; kz++) {
        float4 z = *(const float4*)&g_zpart[(size_t)kz * (B * H4) + (size_t)b * H4 + np];
        zx += z.x; zy += z.y; zz += z.z; zw += z.w;
    }
    const float4 bb = *(const float4*)&bias4[np];
    const float4 ww = *(const float4*)&wiv4[np];

    const float zi = zx + bb.x + xb * ww.x;
    const float zf = zy + bb.y + xb * ww.y;
    const float zg = zz + bb.z + xb * ww.z;
    const float zo = zw + bb.w + xb * ww.w;

    const float c  = sigmoid_acc(zf) * g_c[idx] + sigmoid_acc(zi) * tanh_acc(zg);
    const float hn = sigmoid_acc(zo) * tanh_acc(c);
    g_c[idx] = c;
    g_h[p ^ 1][idx] = hn;
    if (!DEC) {
        const size_t eo = ((size_t)b * L + t) * H + h;
        g_enc_out[eo]  = hn;
        g_enc_outh[eo] = __float2bfloat16_rn(hn);
    }
    if (DEC && h == 0) {
        g_dec_in[p ^ 1][b] = (float)xs[b * L + argsort[b * L + t]];
    }
}

// ---------------- attention (proven): q-reduce + scores + softmax + context ---------------
__global__ void __launch_bounds__(256) k_attn(const float* __restrict__ vt,
                                              float* __restrict__ out, int t) {
    __shared__ float q_s[H];
    __shared__ float vt_s[H];
    __shared__ float sc[L];
    __shared__ float aj[L];

    const int b = blockIdx.x;
    const int tid = threadIdx.x;
    const int lane = tid & 31;
    const int w = tid >> 5;

    for (int i = tid; i < H; i += 256) {
        float s = 0.0f;
#pragma unroll
        for (int sp = 0; sp < 8; sp++)
            s += g_qpart[(size_t)sp * (B * H) + b * H + i];
        q_s[i]  = s;
        vt_s[i] = vt[i];
    }
    __syncthreads();

#pragma unroll 1
    for (int li = 0; li < 16; li++) {
        const int l = w * 16 + li;
        const uint4* e8 = (const uint4*)(g_enc_w1h + (size_t)(b * L + l) * H);
        float s = 0.f;
#pragma unroll
        for (int j = 0; j < 2; j++) {
            const int base = (lane + j * 32) * 8;
            uint4 u = e8[lane + j * 32];
            float4 q0 = *(const float4*)&q_s[base];
            float4 q1 = *(const float4*)&q_s[base + 4];
            float4 v0 = *(const float4*)&vt_s[base];
            float4 v1 = *(const float4*)&vt_s[base + 4];
            float2 e0 = __bfloat1622float2(*(__nv_bfloat162*)&u.x);
            float2 e1 = __bfloat1622float2(*(__nv_bfloat162*)&u.y);
            float2 e2 = __bfloat1622float2(*(__nv_bfloat162*)&u.z);
            float2 e3 = __bfloat1622float2(*(__nv_bfloat162*)&u.w);
            s += v0.x * tanh_fast(e0.x + q0.x);
            s += v0.y * tanh_fast(e0.y + q0.y);
            s += v0.z * tanh_fast(e1.x + q0.z);
            s += v0.w * tanh_fast(e1.y + q0.w);
            s += v1.x * tanh_fast(e2.x + q1.x);
            s += v1.y * tanh_fast(e2.y + q1.y);
            s += v1.z * tanh_fast(e3.x + q1.z);
            s += v1.w * tanh_fast(e3.y + q1.w);
        }
#pragma unroll
        for (int o = 16; o > 0; o >>= 1) s += __shfl_xor_sync(0xffffffffu, s, o);
        if (lane == 0) sc[l] = s;
    }
    __syncthreads();

    if (w == 0) {
        float sv[4];
        float m = -1e30f;
#pragma unroll
        for (int k = 0; k < 4; k++) { sv[k] = sc[lane * 4 + k]; m = fmaxf(m, sv[k]); }
#pragma unroll
        for (int o = 16; o > 0; o >>= 1) m = fmaxf(m, __shfl_xor_sync(0xffffffffu, m, o));
        float e[4], sum = 0.f;
#pragma unroll
        for (int k = 0; k < 4; k++) { e[k] = __expf(sv[k] - m); sum += e[k]; }
#pragma unroll
        for (int o = 16; o > 0; o >>= 1) sum += __shfl_xor_sync(0xffffffffu, sum, o);
        const float ls  = __logf(sum);
        const float inv = 1.0f / sum;
        float* orow = out + ((size_t)b * L + t) * L;
#pragma unroll
        for (int k = 0; k < 4; k++) {
            orow[lane * 4 + k] = sv[k] - m - ls;
            aj[lane * 4 + k]   = e[k] * inv;
        }
    }
    __syncthreads();

    const int h2 = tid * 2;
    float ax = 0.f, ay = 0.f;
    const __nv_bfloat162* base =
        (const __nv_bfloat162*)(g_enc_outh + (size_t)b * L * H + h2);
#pragma unroll 4
    for (int l = 0; l < L; l++) {
        const float a = aj[l];
        float2 v = __bfloat1622float2(base[(size_t)l * (H / 2)]);
        ax += a * v.x;
        ay += a * v.y;
    }
    g_ctx[b * H + h2]     = ax;
    g_ctx[b * H + h2 + 1] = ay;
}

}  // namespace

extern "C" void kernel_launch(void* const* d_in, const int* in_sizes, int n_in,
                              void* d_out, int out_size) {
    (void)in_sizes; (void)n_in; (void)out_size;
    const int*   xs      = (const int*)d_in[0];
    const int*   argsort = (const int*)d_in[2];
    const float* enc_Wi  = (const float*)d_in[3];
    const float* enc_Wh  = (const float*)d_in[4];
    const float* enc_b   = (const float*)d_in[5];
    const float* dec_Wi  = (const float*)d_in[6];
    const float* dec_Wh  = (const float*)d_in[7];
    const float* dec_b   = (const float*)d_in[8];
    const float* w1      = (const float*)d_in[9];
    const float* w2      = (const float*)d_in[10];
    const float* vt      = (const float*)d_in[11];
    float* out = (float*)d_out;

    float *p_h, *p_ctx, *p_encout, *p_ew4, *p_eb4, *p_ewi4, *p_dw4, *p_db4, *p_dwi4;
    float *p_zpart, *p_qpart;
    cudaGetSymbolAddress((void**)&p_h,      g_h);
    cudaGetSymbolAddress((void**)&p_ctx,    g_ctx);
    cudaGetSymbolAddress((void**)&p_encout, g_enc_out);
    cudaGetSymbolAddress((void**)&p_ew4,    g_ew4);
    cudaGetSymbolAddress((void**)&p_eb4,    g_eb4);
    cudaGetSymbolAddress((void**)&p_ewi4,   g_ewi4);
    cudaGetSymbolAddress((void**)&p_dw4,    g_dw4);
    cudaGetSymbolAddress((void**)&p_db4,    g_db4);
    cudaGetSymbolAddress((void**)&p_dwi4,   g_dwi4);
    cudaGetSymbolAddress((void**)&p_zpart,  g_zpart);
    cudaGetSymbolAddress((void**)&p_qpart,  g_qpart);

    k_init<<<128, 256>>>();
    k_repack_enc<<<256, 256>>>(enc_Wh, enc_b, enc_Wi);
    k_repack_dec<<<512, 256>>>(dec_Wi, dec_Wh, dec_b);

    const dim3 gates_grid(B * H / 256);             // 512
    const dim3 lstm_gemm(H4 / 64, B / 64, 4);       // (32, 4, 4) = 512 CTAs
    const dim3 q_gemm(H / 64, B / 64, 8);           // (8, 4, 8)  = 256 CTAs
    const dim3 encw1_grid(H / 64, (B * L) / 64, 1); // (8, 512)

    // ---- encoder: 128 steps of tf32-mma split-K GEMM + gates ----
    for (int t = 0; t < L; t++) {
        const float* hp = p_h + (size_t)(t & 1) * (B * H);
        k_mma<512, 4, false, 0><<<lstm_gemm, 128>>>(p_ew4, hp, nullptr, p_zpart);
        k_gates<false><<<gates_grid, 256>>>(p_eb4, p_ewi4, xs, nullptr, t);
    }

    // ---- hoisted projection enc_w1 = enc_out @ w1^T (tf32 mma, bf16 out) ----
    k_mma<512, 1, false, 1><<<encw1_grid, 128>>>(w1, p_encout, nullptr, nullptr);

    // ---- decoder: 128 steps of q-proj -> attention -> LSTM GEMM + gates ----
    for (int t = 0; t < L; t++) {
        const float* hp = p_h + (size_t)(t & 1) * (B * H);
        k_mma<512, 8, false, 0><<<q_gemm, 128>>>(w2, hp, nullptr, p_qpart);
        k_attn<<<B, 256>>>(vt, out, t);
        k_mma<1024, 4, true, 0><<<lstm_gemm, 128>>>(p_dw4, p_ctx, hp, p_zpart);
        k_gates<true><<<gates_grid, 256>>>(p_db4, p_dwi4, xs, argsort, t);
    }
}